// round 3
// baseline (speedup 1.0000x reference)
#include <cuda_runtime.h>
#include <math.h>

#define MAXN 1024

// ---------------- persistent device state (static, no runtime alloc) ----------------
__device__ float  g_S[MAXN * MAXN];      // symmetric slot-distance matrix (live rows/cols valid)
__device__ double g_T[MAXN * MAXN];      // T[slot][leaf] = sum_{i in leaves(slot)} Wsym[i][leaf]
__device__ float  g_values[MAXN];
__device__ int    g_indices[MAXN];
__device__ int    g_label[MAXN];
__device__ unsigned g_keymax;            // order-encoded max(X)
__device__ unsigned g_keyabs;            // order-encoded max(|X|)

// order-preserving float <-> unsigned encoding (for atomicMax)
__device__ __forceinline__ unsigned enc_f(float f) {
    unsigned u = __float_as_uint(f);
    return (u & 0x80000000u) ? ~u : (u | 0x80000000u);
}
__device__ __forceinline__ float dec_f(unsigned k) {
    unsigned u = (k & 0x80000000u) ? (k ^ 0x80000000u) : ~k;
    return __uint_as_float(u);
}

__global__ void k_reset() { g_keymax = 0u; g_keyabs = 0u; }

__global__ void k_reduce(const float* __restrict__ X, int n) {
    float m = -INFINITY, a = 0.0f;
    for (int i = blockIdx.x * blockDim.x + threadIdx.x; i < n; i += gridDim.x * blockDim.x) {
        float v = X[i];
        m = fmaxf(m, v);
        a = fmaxf(a, fabsf(v));
    }
#pragma unroll
    for (int o = 16; o; o >>= 1) {
        m = fmaxf(m, __shfl_down_sync(0xffffffffu, m, o));
        a = fmaxf(a, __shfl_down_sync(0xffffffffu, a, o));
    }
    __shared__ float sm[32], sa[32];
    int lane = threadIdx.x & 31, wid = threadIdx.x >> 5;
    if (lane == 0) { sm[wid] = m; sa[wid] = a; }
    __syncthreads();
    if (wid == 0) {
        int nw = (blockDim.x + 31) >> 5;
        m = (lane < nw) ? sm[lane] : -INFINITY;
        a = (lane < nw) ? sa[lane] : 0.0f;
#pragma unroll
        for (int o = 16; o; o >>= 1) {
            m = fmaxf(m, __shfl_down_sync(0xffffffffu, m, o));
            a = fmaxf(a, __shfl_down_sync(0xffffffffu, a, o));
        }
        if (lane == 0) {
            atomicMax(&g_keymax, enc_f(m));
            atomicMax(&g_keyabs, enc_f(a));
        }
    }
}

__global__ void k_initS(const float* __restrict__ X, int D) {
    float maxd = dec_f(g_keyabs) * 1000.0f;
    float msim = dec_f(g_keymax);
    int n = D * D;
    for (int idx = blockIdx.x * blockDim.x + threadIdx.x; idx < n; idx += gridDim.x * blockDim.x) {
        int i = idx / D;
        int j = idx - i * D;
        g_S[idx] = (i == j) ? maxd : (msim - X[idx]);
    }
}

__global__ void k_initT(const float* __restrict__ W, int D) {
    int n = D * D;
    for (int idx = blockIdx.x * blockDim.x + threadIdx.x; idx < n; idx += gridDim.x * blockDim.x) {
        int i = idx / D;
        int j = idx - i * D;
        g_T[idx] = (double)W[idx] + (double)W[j * D + i];
    }
}

// one block per row: values[r] = min_{j>r} S[r][j], indices = lowest argmin
__global__ void k_initVals(int D) {
    int r = blockIdx.x;
    float maxd = dec_f(g_keyabs) * 1000.0f;
    float bv = maxd;
    int bi = 0x7fffffff;
    for (int j = r + 1 + (int)threadIdx.x; j < D; j += blockDim.x) {
        float x = g_S[r * D + j];
        if (x < bv || (x == bv && j < bi)) { bv = x; bi = j; }
    }
#pragma unroll
    for (int o = 16; o; o >>= 1) {
        float ov = __shfl_down_sync(0xffffffffu, bv, o);
        int   oi = __shfl_down_sync(0xffffffffu, bi, o);
        if (ov < bv || (ov == bv && oi < bi)) { bv = ov; bi = oi; }
    }
    __shared__ float sv[8];
    __shared__ int   si[8];
    int lane = threadIdx.x & 31, wid = threadIdx.x >> 5;
    if (lane == 0) { sv[wid] = bv; si[wid] = bi; }
    __syncthreads();
    if (threadIdx.x == 0) {
        int nw = (blockDim.x + 31) >> 5;
        for (int k = 1; k < nw; ++k) {
            if (sv[k] < bv || (sv[k] == bv && si[k] < bi)) { bv = sv[k]; bi = si[k]; }
        }
        g_values[r] = bv;
        g_indices[r] = (bi == 0x7fffffff) ? 0 : bi;
    }
}

// ---------------- the sequential HAC loop: one persistent block ----------------
__global__ void __launch_bounds__(1024, 1) k_hac(int D) {
    const int tid = threadIdx.x;
    const int lane = tid & 31, wid = tid >> 5;
    const int nw = blockDim.x >> 5;

    __shared__ float  s_val[MAXN];
    __shared__ int    s_idx[MAXN];
    __shared__ float  s_newv[MAXN];
    __shared__ float  s_cs[MAXN];
    __shared__ double s_energy[MAXN];
    __shared__ double s_within[MAXN];
    __shared__ int    s_slot[MAXN];
    __shared__ int    s_label[MAXN];
    __shared__ int    s_list[MAXN];
    __shared__ unsigned char s_dead[MAXN];
    __shared__ float  s_rv[32];
    __shared__ int    s_ri[32];
    __shared__ double s_c12[32];
    __shared__ int    sh_m1, sh_m2, sh_take, sh_nrec;
    __shared__ float  sh_cs1, sh_cs2, sh_ncs;

    const float MAXDV = dec_f(g_keyabs) * 1000.0f;

    s_val[tid]    = g_values[tid];
    s_idx[tid]    = g_indices[tid];
    s_cs[tid]     = 1.0f;
    s_energy[tid] = 0.0;
    s_within[tid] = 0.0;
    s_slot[tid]   = tid;
    s_label[tid]  = tid;
    s_dead[tid]   = 0;
    if (tid == 0) sh_nrec = 0;
    __syncthreads();

    for (int step = 0; step < D - 1; ++step) {
        // ---- A. global argmin over values (lowest-index tie-break) ----
        float v = s_val[tid];
        int   ix = tid;
#pragma unroll
        for (int o = 16; o; o >>= 1) {
            float ov = __shfl_down_sync(0xffffffffu, v, o);
            int   oi = __shfl_down_sync(0xffffffffu, ix, o);
            if (ov < v || (ov == v && oi < ix)) { v = ov; ix = oi; }
        }
        if (lane == 0) { s_rv[wid] = v; s_ri[wid] = ix; }
        __syncthreads();
        if (wid == 0) {
            v  = (lane < nw) ? s_rv[lane] : MAXDV;
            ix = (lane < nw) ? s_ri[lane] : 0x7fffffff;
#pragma unroll
            for (int o = 16; o; o >>= 1) {
                float ov = __shfl_down_sync(0xffffffffu, v, o);
                int   oi = __shfl_down_sync(0xffffffffu, ix, o);
                if (ov < v || (ov == v && oi < ix)) { v = ov; ix = oi; }
            }
            if (lane == 0) {
                int m1 = ix;
                int m2 = s_idx[m1];
                float cs1 = s_cs[m1], cs2 = s_cs[m2];
                s_cs[m1] = cs1 + cs2;
                s_dead[m2] = 1;
                sh_m1 = m1; sh_m2 = m2;
                sh_cs1 = cs1; sh_cs2 = cs2; sh_ncs = cs1 + cs2;
            }
        }
        __syncthreads();
        const int m1 = sh_m1, m2 = sh_m2;
        const float cs1 = sh_cs1, cs2 = sh_cs2, ncs = sh_ncs;

        // ---- B. fully coalesced bulk pass ----
        {
            // S: read rows m1,m2 (contiguous), write row m1 (contiguous),
            //    write col m1 only for live rows (strided, shrinks over time)
            const int dead = s_dead[tid];
            float a = g_S[(size_t)m1 * D + tid];
            float b = g_S[(size_t)m2 * D + tid];
            float nv = (tid == m1 || dead)
                           ? MAXDV
                           : __fdiv_rn(__fadd_rn(__fmul_rn(a, cs1), __fmul_rn(b, cs2)), ncs);
            s_newv[tid] = nv;
            g_S[(size_t)m1 * D + tid] = nv;
            if (!dead) g_S[(size_t)tid * D + m1] = nv;

            // cross rows over LEAF columns: contiguous add + fused c12 reduction
            double t1 = g_T[(size_t)m1 * D + tid];
            double t2 = g_T[(size_t)m2 * D + tid];
            g_T[(size_t)m1 * D + tid] = t1 + t2;
            double part = (s_slot[tid] == m2) ? t1 : 0.0;
#pragma unroll
            for (int o = 16; o; o >>= 1)
                part += __shfl_down_sync(0xffffffffu, part, o);
            if (lane == 0) s_c12[wid] = part;
        }
        __syncthreads();

        // ---- C. take decision (thread 0) + slot remap + incremental values ----
        if (tid == 0) {
            double c12 = 0.0;
            for (int k = 0; k < nw; ++k) c12 += s_c12[k];
            double me = s_within[m1] + s_within[m2] + c12;
            double es = s_energy[m1] + s_energy[m2];
            int take = (me >= es) ? 1 : 0;
            s_energy[m1] = take ? me : es;
            s_within[m1] = me;
            sh_take = take;
        }
        if (s_slot[tid] == m2) s_slot[tid] = m1;
        if (tid == m2) {
            s_val[tid] = MAXDV;
        } else if (tid == m1) {
            int p = atomicAdd(&sh_nrec, 1);
            s_list[p] = tid;
        } else if (s_val[tid] != MAXDV) {
            int oi = s_idx[tid];
            if (oi == m1 || oi == m2) {
                int p = atomicAdd(&sh_nrec, 1);
                s_list[p] = tid;
            } else if (m1 > tid) {
                float cand = s_newv[tid];
                if (cand < s_val[tid] || (cand == s_val[tid] && m1 < oi)) {
                    s_val[tid] = cand;
                    s_idx[tid] = m1;
                }
            }
        }
        __syncthreads();

        // ---- D. labels + row-min recomputes (one warp per invalidated row) ----
        if (sh_take && s_slot[tid] == m1) s_label[tid] = D + step;

        int nrec = sh_nrec;
        for (int k = wid; k < nrec; k += nw) {
            int r = s_list[k];
            float bv = MAXDV;
            int bi = 0x7fffffff;
            if (r == m1) {
                for (int j = r + 1 + lane; j < D; j += 32) {
                    if (s_dead[j]) continue;
                    float x = s_newv[j];
                    if (x < bv || (x == bv && j < bi)) { bv = x; bi = j; }
                }
            } else {
                for (int j = r + 1 + lane; j < D; j += 32) {
                    if (s_dead[j]) continue;
                    float x = g_S[(size_t)r * D + j];
                    if (x < bv || (x == bv && j < bi)) { bv = x; bi = j; }
                }
            }
#pragma unroll
            for (int o = 16; o; o >>= 1) {
                float ov = __shfl_down_sync(0xffffffffu, bv, o);
                int   oi2 = __shfl_down_sync(0xffffffffu, bi, o);
                if (ov < bv || (ov == bv && oi2 < bi)) { bv = ov; bi = oi2; }
            }
            if (lane == 0) {
                s_val[r] = bv;
                s_idx[r] = (bi == 0x7fffffff) ? 0 : bi;
            }
        }
        __syncthreads();
        if (tid == 0) sh_nrec = 0;  // consumed only after next step's A-phase syncs
    }

    g_label[tid] = s_label[tid];
}

// R[i][j] = 1 iff i==j or label[i]==label[j] (labels only collide via take-merges)
__global__ void k_out(float* __restrict__ out, int D) {
    int n = D * D;
    for (int idx = blockIdx.x * blockDim.x + threadIdx.x; idx < n; idx += gridDim.x * blockDim.x) {
        int i = idx / D;
        int j = idx - i * D;
        out[idx] = (i == j || __ldg(&g_label[i]) == __ldg(&g_label[j])) ? 1.0f : 0.0f;
    }
}

extern "C" void kernel_launch(void* const* d_in, const int* in_sizes, int n_in,
                              void* d_out, int out_size) {
    const float* X = (const float*)d_in[0];
    const float* W = (const float*)d_in[1];
    int n = in_sizes[0];
    int D = (int)(sqrt((double)n) + 0.5);
    if (D > MAXN || D < 32) return;

    k_reset<<<1, 1>>>();
    k_reduce<<<256, 256>>>(X, n);
    k_initS<<<2048, 256>>>(X, D);
    k_initT<<<2048, 256>>>(W, D);
    k_initVals<<<D, 256>>>(D);
    k_hac<<<1, D>>>(D);
    k_out<<<2048, 256>>>((float*)d_out, D);
}

// round 4
// speedup vs baseline: 1.1608x; 1.1608x over previous
#include <cuda_runtime.h>
#include <math.h>

#define MAXN 1024

// ---------------- persistent device state (static, no runtime alloc) ----------------
__device__ float  g_S[MAXN * MAXN];      // symmetric slot-distance matrix (live entries valid)
__device__ double g_T[MAXN * MAXN];      // T[slot][leaf] = sum_{i in leaves(slot)} Wsym[i][leaf]
__device__ float  g_values[MAXN];
__device__ int    g_indices[MAXN];
__device__ int    g_label[MAXN];
__device__ unsigned g_keymax;            // order-encoded max(X)
__device__ unsigned g_keyabs;            // order-encoded max(|X|)

__device__ __forceinline__ unsigned enc_f(float f) {
    unsigned u = __float_as_uint(f);
    return (u & 0x80000000u) ? ~u : (u | 0x80000000u);
}
__device__ __forceinline__ float dec_f(unsigned k) {
    unsigned u = (k & 0x80000000u) ? (k ^ 0x80000000u) : ~k;
    return __uint_as_float(u);
}

__global__ void k_reset() { g_keymax = 0u; g_keyabs = 0u; }

__global__ void k_reduce(const float* __restrict__ X, int n) {
    float m = -INFINITY, a = 0.0f;
    for (int i = blockIdx.x * blockDim.x + threadIdx.x; i < n; i += gridDim.x * blockDim.x) {
        float v = X[i];
        m = fmaxf(m, v);
        a = fmaxf(a, fabsf(v));
    }
#pragma unroll
    for (int o = 16; o; o >>= 1) {
        m = fmaxf(m, __shfl_down_sync(0xffffffffu, m, o));
        a = fmaxf(a, __shfl_down_sync(0xffffffffu, a, o));
    }
    __shared__ float sm[32], sa[32];
    int lane = threadIdx.x & 31, wid = threadIdx.x >> 5;
    if (lane == 0) { sm[wid] = m; sa[wid] = a; }
    __syncthreads();
    if (wid == 0) {
        int nw = (blockDim.x + 31) >> 5;
        m = (lane < nw) ? sm[lane] : -INFINITY;
        a = (lane < nw) ? sa[lane] : 0.0f;
#pragma unroll
        for (int o = 16; o; o >>= 1) {
            m = fmaxf(m, __shfl_down_sync(0xffffffffu, m, o));
            a = fmaxf(a, __shfl_down_sync(0xffffffffu, a, o));
        }
        if (lane == 0) {
            atomicMax(&g_keymax, enc_f(m));
            atomicMax(&g_keyabs, enc_f(a));
        }
    }
}

__global__ void k_initS(const float* __restrict__ X, int D) {
    float maxd = dec_f(g_keyabs) * 1000.0f;
    float msim = dec_f(g_keymax);
    int n = D * D;
    for (int idx = blockIdx.x * blockDim.x + threadIdx.x; idx < n; idx += gridDim.x * blockDim.x) {
        int i = idx / D;
        int j = idx - i * D;
        g_S[idx] = (i == j) ? maxd : (msim - X[idx]);
    }
}

__global__ void k_initT(const float* __restrict__ W, int D) {
    int n = D * D;
    for (int idx = blockIdx.x * blockDim.x + threadIdx.x; idx < n; idx += gridDim.x * blockDim.x) {
        int i = idx / D;
        int j = idx - i * D;
        g_T[idx] = (double)W[idx] + (double)W[j * D + i];
    }
}

// one block per row: values[r] = min_{j>r} S[r][j], indices = lowest argmin
__global__ void k_initVals(int D) {
    int r = blockIdx.x;
    float maxd = dec_f(g_keyabs) * 1000.0f;
    float bv = maxd;
    int bi = 0x7fffffff;
    for (int j = r + 1 + (int)threadIdx.x; j < D; j += blockDim.x) {
        float x = g_S[r * D + j];
        if (x < bv || (x == bv && j < bi)) { bv = x; bi = j; }
    }
#pragma unroll
    for (int o = 16; o; o >>= 1) {
        float ov = __shfl_down_sync(0xffffffffu, bv, o);
        int   oi = __shfl_down_sync(0xffffffffu, bi, o);
        if (ov < bv || (ov == bv && oi < bi)) { bv = ov; bi = oi; }
    }
    __shared__ float sv[8];
    __shared__ int   si[8];
    int lane = threadIdx.x & 31, wid = threadIdx.x >> 5;
    if (lane == 0) { sv[wid] = bv; si[wid] = bi; }
    __syncthreads();
    if (threadIdx.x == 0) {
        int nw = (blockDim.x + 31) >> 5;
        for (int k = 1; k < nw; ++k) {
            if (sv[k] < bv || (sv[k] == bv && si[k] < bi)) { bv = sv[k]; bi = si[k]; }
        }
        g_values[r] = bv;
        g_indices[r] = (bi == 0x7fffffff) ? 0 : bi;
    }
}

// ---------------- the sequential HAC loop: one persistent block ----------------
__global__ void __launch_bounds__(1024, 1) k_hac(int D) {
    const int tid = threadIdx.x;
    const int lane = tid & 31, wid = tid >> 5;
    const int nw = blockDim.x >> 5;

    __shared__ float  s_val[MAXN];
    __shared__ int    s_idx[MAXN];
    __shared__ float  s_newv[MAXN];
    __shared__ float  s_cs[MAXN];
    __shared__ double s_energy[MAXN];
    __shared__ double s_within[MAXN];
    __shared__ int    s_slot[MAXN];
    __shared__ int    s_label[MAXN];
    __shared__ int    s_list[MAXN];
    __shared__ unsigned char s_dead[MAXN];
    __shared__ float  s_rv[32];
    __shared__ int    s_ri[32];
    __shared__ double s_c12[32];
    __shared__ int    sh_m1, sh_m2, sh_take, sh_nrec;
    __shared__ float  sh_cs1, sh_cs2, sh_ncs;

    const float MAXDV = dec_f(g_keyabs) * 1000.0f;

    s_val[tid]    = g_values[tid];
    s_idx[tid]    = g_indices[tid];
    s_cs[tid]     = 1.0f;
    s_energy[tid] = 0.0;
    s_within[tid] = 0.0;
    s_slot[tid]   = tid;
    s_label[tid]  = tid;
    s_dead[tid]   = 0;
    if (tid == 0) sh_nrec = 0;
    __syncthreads();

    for (int step = 0; step < D - 1; ++step) {
        // ==== A. global argmin over values (lowest-index tie-break), leader picks ====
        float v = s_val[tid];
        int   ix = tid;
#pragma unroll
        for (int o = 16; o; o >>= 1) {
            float ov = __shfl_down_sync(0xffffffffu, v, o);
            int   oi = __shfl_down_sync(0xffffffffu, ix, o);
            if (ov < v || (ov == v && oi < ix)) { v = ov; ix = oi; }
        }
        if (lane == 0) { s_rv[wid] = v; s_ri[wid] = ix; }
        __syncthreads();   // sync 1
        if (wid == 0) {
            v  = (lane < nw) ? s_rv[lane] : MAXDV;
            ix = (lane < nw) ? s_ri[lane] : 0x7fffffff;
#pragma unroll
            for (int o = 16; o; o >>= 1) {
                float ov = __shfl_down_sync(0xffffffffu, v, o);
                int   oi = __shfl_down_sync(0xffffffffu, ix, o);
                if (ov < v || (ov == v && oi < ix)) { v = ov; ix = oi; }
            }
            if (lane == 0) {
                int m1 = ix;
                int m2 = s_idx[m1];
                float cs1 = s_cs[m1], cs2 = s_cs[m2];
                s_cs[m1] = cs1 + cs2;
                s_dead[m2] = 1;
                sh_m1 = m1; sh_m2 = m2;
                sh_cs1 = cs1; sh_cs2 = cs2; sh_ncs = cs1 + cs2;
            }
        }
        __syncthreads();   // sync 2
        const int m1 = sh_m1, m2 = sh_m2;
        const float cs1 = sh_cs1, cs2 = sh_cs2, ncs = sh_ncs;

        // ==== B. coalesced bulk pass + own-element value maintenance ====
        {
            const int dead = s_dead[tid];
            float a = g_S[(size_t)m1 * D + tid];
            float b = g_S[(size_t)m2 * D + tid];
            double t1 = g_T[(size_t)m1 * D + tid];
            double t2 = g_T[(size_t)m2 * D + tid];

            float nv = (tid == m1 || dead)
                           ? MAXDV
                           : __fdiv_rn(__fadd_rn(__fmul_rn(a, cs1), __fmul_rn(b, cs2)), ncs);
            s_newv[tid] = nv;
            g_S[(size_t)m1 * D + tid] = nv;           // contiguous row store
            if (!dead) g_S[(size_t)tid * D + m1] = nv; // only strided pass left

            g_T[(size_t)m1 * D + tid] = t1 + t2;       // contiguous row RMW

            double part = (s_slot[tid] == m2) ? t1 : 0.0;  // c12 partial (pre-remap slot)
#pragma unroll
            for (int o = 16; o; o >>= 1)
                part += __shfl_down_sync(0xffffffffu, part, o);
            if (lane == 0) s_c12[wid] = part;

            // slot remap + incremental values (own element only)
            if (s_slot[tid] == m2) s_slot[tid] = m1;
            if (tid == m2) {
                s_val[tid] = MAXDV;
            } else if (tid == m1) {
                int p = atomicAdd(&sh_nrec, 1);
                s_list[p] = tid;
            } else if (s_val[tid] != MAXDV) {
                int oi = s_idx[tid];
                if (oi == m1 || oi == m2) {
                    int p = atomicAdd(&sh_nrec, 1);
                    s_list[p] = tid;
                } else if (m1 > tid) {
                    float cand = nv;
                    if (cand < s_val[tid] || (cand == s_val[tid] && m1 < oi)) {
                        s_val[tid] = cand;
                        s_idx[tid] = m1;
                    }
                }
            }
        }
        __syncthreads();   // sync 3

        // ==== C. warp0: take decision (tree-reduced fp64); warps 1..: row-min recomputes ====
        const int nrec = sh_nrec;
        if (wid == 0) {
            double c = (lane < nw) ? s_c12[lane] : 0.0;
#pragma unroll
            for (int o = 16; o; o >>= 1)
                c += __shfl_down_sync(0xffffffffu, c, o);
            if (lane == 0) {
                double me = s_within[m1] + s_within[m2] + c;
                double es = s_energy[m1] + s_energy[m2];
                int take = (me >= es) ? 1 : 0;
                s_energy[m1] = take ? me : es;
                s_within[m1] = me;
                sh_take = take;
            }
        } else {
            for (int k = wid - 1; k < nrec; k += nw - 1) {
                int r = s_list[k];
                float bv = MAXDV;
                int bi = 0x7fffffff;
                if (r == m1) {
                    for (int j = r + 1 + lane; j < D; j += 32) {
                        float x = s_newv[j];   // dead j already MAXDV here
                        if (x < bv || (x == bv && j < bi)) { bv = x; bi = j; }
                    }
                } else {
                    for (int j = r + 1 + lane; j < D; j += 32) {
                        if (s_dead[j]) continue;
                        float x = g_S[(size_t)r * D + j];
                        if (x < bv || (x == bv && j < bi)) { bv = x; bi = j; }
                    }
                }
#pragma unroll
                for (int o = 16; o; o >>= 1) {
                    float ov = __shfl_down_sync(0xffffffffu, bv, o);
                    int   oi2 = __shfl_down_sync(0xffffffffu, bi, o);
                    if (ov < bv || (ov == bv && oi2 < bi)) { bv = ov; bi = oi2; }
                }
                if (lane == 0) {
                    s_val[r] = bv;
                    s_idx[r] = (bi == 0x7fffffff) ? 0 : bi;
                }
            }
        }
        __syncthreads();   // sync 4

        // ==== D. label write (needs take) — no sync needed before next step ====
        if (sh_take && s_slot[tid] == m1) s_label[tid] = D + step;
        if (tid == 0) sh_nrec = 0;   // next atomicAdd is beyond next step's sync 1
    }

    __syncthreads();
    g_label[tid] = s_label[tid];
}

// R[i][j] = 1 iff i==j or label[i]==label[j] (labels only collide via take-merges)
__global__ void k_out(float* __restrict__ out, int D) {
    int n = D * D;
    for (int idx = blockIdx.x * blockDim.x + threadIdx.x; idx < n; idx += gridDim.x * blockDim.x) {
        int i = idx / D;
        int j = idx - i * D;
        out[idx] = (i == j || __ldg(&g_label[i]) == __ldg(&g_label[j])) ? 1.0f : 0.0f;
    }
}

extern "C" void kernel_launch(void* const* d_in, const int* in_sizes, int n_in,
                              void* d_out, int out_size) {
    const float* X = (const float*)d_in[0];
    const float* W = (const float*)d_in[1];
    int n = in_sizes[0];
    int D = (int)(sqrt((double)n) + 0.5);
    if (D > MAXN || D < 32) return;

    k_reset<<<1, 1>>>();
    k_reduce<<<256, 256>>>(X, n);
    k_initS<<<2048, 256>>>(X, D);
    k_initT<<<2048, 256>>>(W, D);
    k_initVals<<<D, 256>>>(D);
    k_hac<<<1, D>>>(D);
    k_out<<<2048, 256>>>((float*)d_out, D);
}

// round 5
// speedup vs baseline: 1.2562x; 1.0822x over previous
#include <cuda_runtime.h>
#include <math.h>

#define MAXN 1024

// ---------------- persistent device state (static, no runtime alloc) ----------------
__device__ float  g_S[MAXN * MAXN];      // symmetric slot-distance matrix (live entries valid)
__device__ double g_T[MAXN * MAXN];      // T[slot][leaf] = sum_{i in leaves(slot)} Wsym[i][leaf]
__device__ int    g_label[MAXN];
__device__ unsigned g_keymax;            // order-encoded max(X)
__device__ unsigned g_keyabs;            // order-encoded max(|X|)

__device__ __forceinline__ unsigned enc_f(float f) {
    unsigned u = __float_as_uint(f);
    return (u & 0x80000000u) ? ~u : (u | 0x80000000u);
}
__device__ __forceinline__ float dec_f(unsigned k) {
    unsigned u = (k & 0x80000000u) ? (k ^ 0x80000000u) : ~k;
    return __uint_as_float(u);
}

// launch #1
__global__ void k_reset() { g_keymax = 0u; g_keyabs = 0u; }

// launch #2
__global__ void k_reduce(const float* __restrict__ X, int n) {
    float m = -INFINITY, a = 0.0f;
    for (int i = blockIdx.x * blockDim.x + threadIdx.x; i < n; i += gridDim.x * blockDim.x) {
        float v = X[i];
        m = fmaxf(m, v);
        a = fmaxf(a, fabsf(v));
    }
#pragma unroll
    for (int o = 16; o; o >>= 1) {
        m = fmaxf(m, __shfl_down_sync(0xffffffffu, m, o));
        a = fmaxf(a, __shfl_down_sync(0xffffffffu, a, o));
    }
    __shared__ float sm[32], sa[32];
    int lane = threadIdx.x & 31, wid = threadIdx.x >> 5;
    if (lane == 0) { sm[wid] = m; sa[wid] = a; }
    __syncthreads();
    if (wid == 0) {
        int nw = (blockDim.x + 31) >> 5;
        m = (lane < nw) ? sm[lane] : -INFINITY;
        a = (lane < nw) ? sa[lane] : 0.0f;
#pragma unroll
        for (int o = 16; o; o >>= 1) {
            m = fmaxf(m, __shfl_down_sync(0xffffffffu, m, o));
            a = fmaxf(a, __shfl_down_sync(0xffffffffu, a, o));
        }
        if (lane == 0) {
            atomicMax(&g_keymax, enc_f(m));
            atomicMax(&g_keyabs, enc_f(a));
        }
    }
}

// launch #3: fused init of S and T
__global__ void k_initST(const float* __restrict__ X, const float* __restrict__ W, int D) {
    float maxd = dec_f(g_keyabs) * 1000.0f;
    float msim = dec_f(g_keymax);
    int n = D * D;
    for (int idx = blockIdx.x * blockDim.x + threadIdx.x; idx < n; idx += gridDim.x * blockDim.x) {
        int i = idx / D;
        int j = idx - i * D;
        g_S[idx] = (i == j) ? maxd : (msim - X[idx]);
        g_T[idx] = (double)W[idx] + (double)W[j * D + i];
    }
}

// launch #4: the sequential HAC loop, one persistent block (profiled slot)
__global__ void __launch_bounds__(1024, 1) k_hac(int D) {
    const int tid = threadIdx.x;
    const int lane = tid & 31, wid = tid >> 5;
    const int nw = blockDim.x >> 5;

    __shared__ float  s_val[MAXN];
    __shared__ int    s_idx[MAXN];
    __shared__ float  s_newv[MAXN];
    __shared__ float  s_cs[MAXN];
    __shared__ double s_energy[MAXN];
    __shared__ double s_within[MAXN];
    __shared__ int    s_slot[MAXN];
    __shared__ int    s_label[MAXN];
    __shared__ int    s_list[MAXN];
    __shared__ unsigned char s_dead[MAXN];
    __shared__ float  s_rv[32];
    __shared__ int    s_ri[32];
    __shared__ double s_c12[32];
    __shared__ int    sh_m1, sh_m2, sh_take, sh_nrec;
    __shared__ float  sh_cs1, sh_cs2, sh_ncs;

    const float MAXDV = dec_f(g_keyabs) * 1000.0f;

    // ---- prologue: per-tid state + initial row-mins (one warp per row) ----
    s_cs[tid]     = 1.0f;
    s_energy[tid] = 0.0;
    s_within[tid] = 0.0;
    s_slot[tid]   = tid;
    s_label[tid]  = tid;
    s_dead[tid]   = 0;
    if (tid == 0) sh_nrec = 0;

    for (int r = wid; r < D; r += nw) {
        float bv = MAXDV;
        int bi = 0x7fffffff;
        for (int j = r + 1 + lane; j < D; j += 32) {
            float x = g_S[(size_t)r * D + j];
            if (x < bv || (x == bv && j < bi)) { bv = x; bi = j; }
        }
#pragma unroll
        for (int o = 16; o; o >>= 1) {
            float ov = __shfl_down_sync(0xffffffffu, bv, o);
            int   oi = __shfl_down_sync(0xffffffffu, bi, o);
            if (ov < bv || (ov == bv && oi < bi)) { bv = ov; bi = oi; }
        }
        if (lane == 0) {
            s_val[r] = bv;
            s_idx[r] = (bi == 0x7fffffff) ? 0 : bi;
        }
    }
    __syncthreads();

    for (int step = 0; step < D - 1; ++step) {
        // ==== A. global argmin over values (lowest-index tie-break) ====
        float v = s_val[tid];
        int   ix = tid;
#pragma unroll
        for (int o = 16; o; o >>= 1) {
            float ov = __shfl_down_sync(0xffffffffu, v, o);
            int   oi = __shfl_down_sync(0xffffffffu, ix, o);
            if (ov < v || (ov == v && oi < ix)) { v = ov; ix = oi; }
        }
        if (lane == 0) { s_rv[wid] = v; s_ri[wid] = ix; }
        __syncthreads();   // sync 1
        if (wid == 0) {
            v  = (lane < nw) ? s_rv[lane] : MAXDV;
            ix = (lane < nw) ? s_ri[lane] : 0x7fffffff;
#pragma unroll
            for (int o = 16; o; o >>= 1) {
                float ov = __shfl_down_sync(0xffffffffu, v, o);
                int   oi = __shfl_down_sync(0xffffffffu, ix, o);
                if (ov < v || (ov == v && oi < ix)) { v = ov; ix = oi; }
            }
            if (lane == 0) {
                int m1 = ix;
                int m2 = s_idx[m1];
                float cs1 = s_cs[m1], cs2 = s_cs[m2];
                s_cs[m1] = cs1 + cs2;
                s_dead[m2] = 1;
                sh_m1 = m1; sh_m2 = m2;
                sh_cs1 = cs1; sh_cs2 = cs2; sh_ncs = cs1 + cs2;
            }
        }
        __syncthreads();   // sync 2
        const int m1 = sh_m1, m2 = sh_m2;
        const float cs1 = sh_cs1, cs2 = sh_cs2, ncs = sh_ncs;

        // ==== B. contiguous bulk pass + own-element value maintenance ====
        {
            const int dead = s_dead[tid];
            float a = g_S[(size_t)m1 * D + tid];
            float b = g_S[(size_t)m2 * D + tid];
            double t1 = g_T[(size_t)m1 * D + tid];
            double t2 = g_T[(size_t)m2 * D + tid];

            float nv = (tid == m1 || dead)
                           ? MAXDV
                           : __fdiv_rn(__fadd_rn(__fmul_rn(a, cs1), __fmul_rn(b, cs2)), ncs);
            s_newv[tid] = nv;
            g_S[(size_t)m1 * D + tid] = nv;        // contiguous row store
            g_T[(size_t)m1 * D + tid] = t1 + t2;   // contiguous row RMW

            // c12 partial: only warps with contributions run the fp64 tree
            double part = (s_slot[tid] == m2) ? t1 : 0.0;
            unsigned any = __ballot_sync(0xffffffffu, part != 0.0);
            if (any) {
#pragma unroll
                for (int o = 16; o; o >>= 1)
                    part += __shfl_down_sync(0xffffffffu, part, o);
            }
            if (lane == 0) s_c12[wid] = part;

            // slot remap + incremental values (own element only)
            if (s_slot[tid] == m2) s_slot[tid] = m1;
            if (tid == m2) {
                s_val[tid] = MAXDV;
            } else if (tid == m1) {
                int p = atomicAdd(&sh_nrec, 1);
                s_list[p] = tid;
            } else if (s_val[tid] != MAXDV) {
                int oi = s_idx[tid];
                if (oi == m1 || oi == m2) {
                    int p = atomicAdd(&sh_nrec, 1);
                    s_list[p] = tid;
                } else if (m1 > tid) {
                    float cand = nv;
                    if (cand < s_val[tid] || (cand == s_val[tid] && m1 < oi)) {
                        s_val[tid] = cand;
                        s_idx[tid] = m1;
                    }
                }
            }
        }
        __syncthreads();   // sync 3

        // ==== C. warp0: take decision; warps 1..31: row-min recomputes ====
        // (recomputes read the stale row and substitute s_newv[r] for column m1,
        //  so the strided col-m1 store can be deferred to phase D)
        const int nrec = sh_nrec;
        if (wid == 0) {
            double c = (lane < nw) ? s_c12[lane] : 0.0;
#pragma unroll
            for (int o = 16; o; o >>= 1)
                c += __shfl_down_sync(0xffffffffu, c, o);
            if (lane == 0) {
                double me = s_within[m1] + s_within[m2] + c;
                double es = s_energy[m1] + s_energy[m2];
                int take = (me >= es) ? 1 : 0;
                s_energy[m1] = take ? me : es;
                s_within[m1] = me;
                sh_take = take;
            }
        } else {
            for (int k = wid - 1; k < nrec; k += nw - 1) {
                int r = s_list[k];
                float bv = MAXDV;
                int bi = 0x7fffffff;
                if (r == m1) {
                    for (int j = r + 1 + lane; j < D; j += 32) {
                        float x = s_newv[j];   // dead j already MAXDV here
                        if (x < bv || (x == bv && j < bi)) { bv = x; bi = j; }
                    }
                } else {
                    float sub = s_newv[r];     // new value of S[r][m1]
                    for (int j = r + 1 + lane; j < D; j += 32) {
                        if (s_dead[j]) continue;
                        float x = (j == m1) ? sub : g_S[(size_t)r * D + j];
                        if (x < bv || (x == bv && j < bi)) { bv = x; bi = j; }
                    }
                }
#pragma unroll
                for (int o = 16; o; o >>= 1) {
                    float ov = __shfl_down_sync(0xffffffffu, bv, o);
                    int   oi2 = __shfl_down_sync(0xffffffffu, bi, o);
                    if (ov < bv || (ov == bv && oi2 < bi)) { bv = ov; bi = oi2; }
                }
                if (lane == 0) {
                    s_val[r] = bv;
                    s_idx[r] = (bi == 0x7fffffff) ? 0 : bi;
                }
            }
        }
        __syncthreads();   // sync 4

        // ==== D. deferred col-m1 store (overlaps next step's smem argmin),
        //         labels, nrec reset. Visible before next phase B via syncs 1+2. ====
        if (!s_dead[tid]) g_S[(size_t)tid * D + m1] = s_newv[tid];
        if (sh_take && s_slot[tid] == m1) s_label[tid] = D + step;
        if (tid == 0) sh_nrec = 0;
    }

    __syncthreads();
    g_label[tid] = s_label[tid];
}

// launch #5: R[i][j] = 1 iff i==j or label[i]==label[j]
__global__ void k_out(float* __restrict__ out, int D) {
    int n = D * D;
    for (int idx = blockIdx.x * blockDim.x + threadIdx.x; idx < n; idx += gridDim.x * blockDim.x) {
        int i = idx / D;
        int j = idx - i * D;
        out[idx] = (i == j || __ldg(&g_label[i]) == __ldg(&g_label[j])) ? 1.0f : 0.0f;
    }
}

extern "C" void kernel_launch(void* const* d_in, const int* in_sizes, int n_in,
                              void* d_out, int out_size) {
    const float* X = (const float*)d_in[0];
    const float* W = (const float*)d_in[1];
    int n = in_sizes[0];
    int D = (int)(sqrt((double)n) + 0.5);
    if (D > MAXN || D < 32) return;

    k_reset<<<1, 1>>>();
    k_reduce<<<256, 256>>>(X, n);
    k_initST<<<2048, 256>>>(X, W, D);
    k_hac<<<1, D>>>(D);
    k_out<<<2048, 256>>>((float*)d_out, D);
}

// round 6
// speedup vs baseline: 1.9671x; 1.5659x over previous
#include <cuda_runtime.h>
#include <math.h>

#define MAXN 1024

// ---------------- persistent device state ----------------
__device__ float  g_S[MAXN * MAXN];   // symmetric slot-distance matrix (live entries valid)
__device__ float  g_T[MAXN * MAXN];   // T[slot][leaf] = sum over members(slot) of Wsym[.,leaf]
__device__ int    g_label[MAXN];
__device__ unsigned g_keymax;         // order-encoded max(X)
__device__ unsigned g_keyabs;         // order-encoded max(|X|)

__device__ __forceinline__ unsigned enc_f(float f) {
    unsigned u = __float_as_uint(f);
    return (u & 0x80000000u) ? ~u : (u | 0x80000000u);
}
__device__ __forceinline__ float dec_f(unsigned k) {
    unsigned u = (k & 0x80000000u) ? (k ^ 0x80000000u) : ~k;
    return __uint_as_float(u);
}

__global__ void k_reset() { g_keymax = 0u; g_keyabs = 0u; }

__global__ void k_reduce(const float* __restrict__ X, int n) {
    float m = -INFINITY, a = 0.0f;
    for (int i = blockIdx.x * blockDim.x + threadIdx.x; i < n; i += gridDim.x * blockDim.x) {
        float v = X[i];
        m = fmaxf(m, v);
        a = fmaxf(a, fabsf(v));
    }
#pragma unroll
    for (int o = 16; o; o >>= 1) {
        m = fmaxf(m, __shfl_down_sync(0xffffffffu, m, o));
        a = fmaxf(a, __shfl_down_sync(0xffffffffu, a, o));
    }
    __shared__ float sm[32], sa[32];
    int lane = threadIdx.x & 31, wid = threadIdx.x >> 5;
    if (lane == 0) { sm[wid] = m; sa[wid] = a; }
    __syncthreads();
    if (wid == 0) {
        int nw = (blockDim.x + 31) >> 5;
        m = (lane < nw) ? sm[lane] : -INFINITY;
        a = (lane < nw) ? sa[lane] : 0.0f;
#pragma unroll
        for (int o = 16; o; o >>= 1) {
            m = fmaxf(m, __shfl_down_sync(0xffffffffu, m, o));
            a = fmaxf(a, __shfl_down_sync(0xffffffffu, a, o));
        }
        if (lane == 0) {
            atomicMax(&g_keymax, enc_f(m));
            atomicMax(&g_keyabs, enc_f(a));
        }
    }
}

__global__ void k_initST(const float* __restrict__ X, const float* __restrict__ W, int D) {
    float maxd = dec_f(g_keyabs) * 1000.0f;
    float msim = dec_f(g_keymax);
    int n = D * D;
    for (int idx = blockIdx.x * blockDim.x + threadIdx.x; idx < n; idx += gridDim.x * blockDim.x) {
        int i = idx / D;
        int j = idx - i * D;
        g_S[idx] = (i == j) ? maxd : (msim - X[idx]);
        g_T[idx] = W[idx] + W[j * D + i];
    }
}

// ---------------- the sequential HAC loop: one persistent block ----------------
__global__ void __launch_bounds__(1024, 1) k_hac(int D) {
    const int tid = threadIdx.x;
    const int lane = tid & 31, wid = tid >> 5;
    const int nw = blockDim.x >> 5;

    // packed per-row key: (valbits<<32) | partner_idx   (vals are >=0 -> bit-monotone)
    __shared__ unsigned long long s_vp[MAXN];
    __shared__ float  s_newv[MAXN];
    __shared__ float  s_cs[MAXN];
    __shared__ float  s_within[MAXN];
    __shared__ float  s_energy[MAXN];
    __shared__ short  s_slot[MAXN];
    __shared__ short  s_listA[MAXN];
    __shared__ short  s_listB[MAXN];
    __shared__ short  s_pos[MAXN];
    __shared__ short  s_rlist[MAXN];
    __shared__ short  s_curnode[MAXN];
    __shared__ short  s_parent[2 * MAXN];
    __shared__ unsigned s_takew[(2 * MAXN) / 32];
    __shared__ unsigned long long s_rk[32];
    __shared__ float  s_c12[32];
    __shared__ int    sh_m1, sh_m2, sh_nrec, sh_nact, sh_p2;
    __shared__ int    sh_pm1, sh_pm2, sh_pnode;
    __shared__ float  sh_cs1, sh_cs2, sh_ncs;

    const float MAXDV = dec_f(g_keyabs) * 1000.0f;
    const unsigned MAXDB = __float_as_uint(MAXDV);

    // ---- prologue ----
    s_cs[tid]      = 1.0f;
    s_within[tid]  = 0.0f;
    s_energy[tid]  = 0.0f;
    s_slot[tid]    = (short)tid;
    s_listA[tid]   = (short)tid;
    s_pos[tid]     = (short)tid;
    s_curnode[tid] = (short)tid;
    for (int q = tid; q < 2 * MAXN; q += blockDim.x) s_parent[q] = -1;
    for (int q = tid; q < (2 * MAXN) / 32; q += blockDim.x) s_takew[q] = 0u;
    if (tid < 32) s_c12[tid] = 0.0f;
    if (tid == 0) { sh_nrec = 0; sh_nact = D; }

    // initial row-mins: values[r] = min_{j>r} S[r][j], lowest-index tie-break
    for (int r = wid; r < D; r += nw) {
        unsigned long long best = ((unsigned long long)MAXDB << 32);
        for (int j = r + 1 + lane; j < D; j += 32) {
            float x = g_S[(size_t)r * D + j];
            unsigned long long key = ((unsigned long long)__float_as_uint(x) << 32) | (unsigned)j;
            if (key < best) best = key;
        }
#pragma unroll
        for (int o = 16; o; o >>= 1) {
            unsigned long long ok = __shfl_down_sync(0xffffffffu, best, o);
            if (ok < best) best = ok;
        }
        if (lane == 0) s_vp[r] = best;
    }
    __syncthreads();

    for (int step = 0; step < D - 1; ++step) {
        const short* cur = (step & 1) ? s_listB : s_listA;
        short* nxt = (step & 1) ? s_listA : s_listB;
        const int nact0 = sh_nact;

        // ==== A. argmin over live list (key = valbits<<32 | row, lowest-row tie-break) ====
        unsigned long long k = ~0ull;
        if (tid < nact0) {
            int r = cur[tid];
            k = (s_vp[r] & 0xffffffff00000000ull) | (unsigned)r;
        }
#pragma unroll
        for (int o = 16; o; o >>= 1) {
            unsigned long long ok = __shfl_down_sync(0xffffffffu, k, o);
            if (ok < k) k = ok;
        }
        if (lane == 0) s_rk[wid] = k;
        __syncthreads();   // sync 1
        if (wid == 0) {
            // finalize previous step's take decision (fp32, deterministic order)
            float c = s_c12[lane];
#pragma unroll
            for (int o = 16; o; o >>= 1)
                c += __shfl_down_sync(0xffffffffu, c, o);
            s_c12[lane] = 0.0f;
            unsigned long long k2 = (lane < nw) ? s_rk[lane] : ~0ull;
#pragma unroll
            for (int o = 16; o; o >>= 1) {
                unsigned long long ok = __shfl_down_sync(0xffffffffu, k2, o);
                if (ok < k2) k2 = ok;
            }
            if (lane == 0) {
                if (step > 0) {
                    float me = s_within[sh_pm1] + s_within[sh_pm2] + c;
                    float es = s_energy[sh_pm1] + s_energy[sh_pm2];
                    int tk = (me >= es) ? 1 : 0;
                    s_energy[sh_pm1] = tk ? me : es;
                    s_within[sh_pm1] = me;
                    if (tk) s_takew[sh_pnode >> 5] |= (1u << (sh_pnode & 31));
                }
                int m1 = (int)(k2 & 0xffffffffull);
                unsigned long long vp = s_vp[m1];
                int m2 = (int)(vp & 0xffffffffull);
                float cs1 = s_cs[m1], cs2 = s_cs[m2];
                s_cs[m1] = cs1 + cs2;
                int node = D + step;
                short c1 = s_curnode[m1], c2 = s_curnode[m2];
                s_parent[c1] = (short)node;
                s_parent[c2] = (short)node;
                s_curnode[m1] = (short)node;
                sh_m1 = m1; sh_m2 = m2;
                sh_cs1 = cs1; sh_cs2 = cs2; sh_ncs = cs1 + cs2;
                sh_pm1 = m1; sh_pm2 = m2; sh_pnode = node;
                sh_p2 = s_pos[m2];
                sh_nact = nact0 - 1;
                sh_nrec = 0;
            }
        }
        __syncthreads();   // sync 2
        const int m1 = sh_m1, m2 = sh_m2, nact = sh_nact, p2 = sh_p2;
        const float cs1 = sh_cs1, cs2 = sh_cs2, ncs = sh_ncs;

        // ==== B. sorted shift-delete + live S updates + value maintenance ====
        int j = -1;
        float nv = 0.0f;
        const bool liveT = (tid < nact);
        if (liveT) {
            j = cur[tid + ((tid >= p2) ? 1 : 0)];
            nxt[tid] = (short)j;
            s_pos[j] = (short)tid;
        }
        const int sv = s_slot[tid];
        const bool wasM2 = (sv == m2);
        if (wasM2) s_slot[tid] = (short)m1;
        if (liveT) {
            float a = g_S[(size_t)m1 * D + j];
            float b = g_S[(size_t)m2 * D + j];
            nv = (j == m1)
                     ? MAXDV
                     : __fdiv_rn(__fadd_rn(__fmul_rn(a, cs1), __fmul_rn(b, cs2)), ncs);
            s_newv[j] = nv;
            g_S[(size_t)m1 * D + j] = nv;   // near-coalesced (sorted list)
            unsigned long long vp = s_vp[j];
            unsigned vbits = (unsigned)(vp >> 32);
            if (j == m1) {
                int p = atomicAdd(&sh_nrec, 1);
                s_rlist[p] = (short)j;
            } else if (vbits != MAXDB) {          // frozen rows stay frozen
                int part = (int)(vp & 0xffffffffull);
                if (part == m1 || part == m2) {
                    int p = atomicAdd(&sh_nrec, 1);
                    s_rlist[p] = (short)j;
                } else if (m1 > j) {
                    unsigned long long ck =
                        ((unsigned long long)__float_as_uint(nv) << 32) | (unsigned)m1;
                    if (ck < vp) s_vp[j] = ck;
                }
            }
        }
        __syncthreads();   // sync 3

        // ==== C. T-row add + c12 partials; col-m1 store; row-min recomputes ====
        {
            float t1 = g_T[(size_t)m1 * D + tid];
            float t2 = g_T[(size_t)m2 * D + tid];
            g_T[(size_t)m1 * D + tid] = __fadd_rn(t1, t2);
            unsigned any = __ballot_sync(0xffffffffu, wasM2);
            if (any) {
                float part = wasM2 ? t1 : 0.0f;
#pragma unroll
                for (int o = 16; o; o >>= 1)
                    part += __shfl_down_sync(0xffffffffu, part, o);
                if (lane == 0) s_c12[wid] = part;
            }
        }
        if (liveT) g_S[(size_t)j * D + m1] = nv;   // strided, shrinks with nact

        const int nrec = sh_nrec;
        for (int k2 = wid; k2 < nrec; k2 += nw) {
            int r = s_rlist[k2];
            unsigned long long best = ((unsigned long long)MAXDB << 32);
            if (r == m1) {
                for (int p = lane; p < nact; p += 32) {
                    int jj = nxt[p];
                    if (jj > r) {
                        float x = s_newv[jj];
                        unsigned long long key =
                            ((unsigned long long)__float_as_uint(x) << 32) | (unsigned)jj;
                        if (key < best) best = key;
                    }
                }
            } else {
                float sub = s_newv[r];   // new S[r][m1] (col store may be in flight)
                for (int p = lane; p < nact; p += 32) {
                    int jj = nxt[p];
                    if (jj > r) {
                        float x = (jj == m1) ? sub : g_S[(size_t)r * D + jj];
                        unsigned long long key =
                            ((unsigned long long)__float_as_uint(x) << 32) | (unsigned)jj;
                        if (key < best) best = key;
                    }
                }
            }
#pragma unroll
            for (int o = 16; o; o >>= 1) {
                unsigned long long ok = __shfl_down_sync(0xffffffffu, best, o);
                if (ok < best) best = ok;
            }
            if (lane == 0) s_vp[r] = best;
        }
        __syncthreads();   // sync 4
    }

    // finalize the last step's take decision
    if (wid == 0) {
        float c = s_c12[lane];
#pragma unroll
        for (int o = 16; o; o >>= 1)
            c += __shfl_down_sync(0xffffffffu, c, o);
        if (lane == 0) {
            float me = s_within[sh_pm1] + s_within[sh_pm2] + c;
            float es = s_energy[sh_pm1] + s_energy[sh_pm2];
            if (me >= es) s_takew[sh_pnode >> 5] |= (1u << (sh_pnode & 31));
        }
    }
    __syncthreads();

    // labels: topmost take-flagged ancestor of each leaf (or the leaf itself)
    {
        int node = tid, best = tid;
        int p;
        while ((p = (int)s_parent[node]) >= 0) {
            node = p;
            if ((s_takew[node >> 5] >> (node & 31)) & 1u) best = node;
        }
        g_label[tid] = best;
    }
}

// R[i][j] = 1 iff i==j or label[i]==label[j]
__global__ void k_out(float* __restrict__ out, int D) {
    int n = D * D;
    for (int idx = blockIdx.x * blockDim.x + threadIdx.x; idx < n; idx += gridDim.x * blockDim.x) {
        int i = idx / D;
        int j = idx - i * D;
        out[idx] = (i == j || __ldg(&g_label[i]) == __ldg(&g_label[j])) ? 1.0f : 0.0f;
    }
}

extern "C" void kernel_launch(void* const* d_in, const int* in_sizes, int n_in,
                              void* d_out, int out_size) {
    const float* X = (const float*)d_in[0];
    const float* W = (const float*)d_in[1];
    int n = in_sizes[0];
    int D = (int)(sqrt((double)n) + 0.5);
    if (D > MAXN || D < 32) return;

    k_reset<<<1, 1>>>();
    k_reduce<<<256, 256>>>(X, n);
    k_initST<<<2048, 256>>>(X, W, D);
    k_hac<<<1, D>>>(D);
    k_out<<<2048, 256>>>((float*)d_out, D);
}